// round 2
// baseline (speedup 1.0000x reference)
#include <cuda_runtime.h>
#include <cstdint>
#include <cstddef>

// Problem constants
#define BB   8
#define HH   256
#define NHH  8
#define HDD  32
#define LL   50
#define VV   50257
#define NLL  4
#define FFF  2048
#define EE   1536
#define BOSTOK 50256
#define STEPS 49
#define EPSLN 1e-5f

// ---------------- device scratch (no allocations allowed) ----------------
__device__ float g_mem_[BB*HH];                 // projected memory [B,H]
__device__ float g_tmpv[NLL*BB*HH];             // v_mem per layer
__device__ float g_ca  [NLL*BB*HH];             // cross-attn constant per layer
__device__ float g_xe  [BB*HH];                 // current step embedding (layer-0 input)
__device__ float g_q   [BB*HH];                 // q of current layer
__device__ float g_Kc  [NLL*BB*LL*HH];          // K cache
__device__ float g_Vc  [NLL*BB*LL*HH];          // V cache
__device__ float g_pr  [BB*HH];                 // attn out-proj output
__device__ float g_x2  [NLL*BB*HH];             // x2 (post-LN2) per layer
__device__ float g_yb  [NLL*BB*HH];             // FFN output per layer
__device__ float g_hbuf[BB*FFF];                // FFN hidden
__device__ unsigned long long g_am[BB];         // packed argmax (val<<32 | inv idx)

// ---------------- helpers ----------------
__device__ __forceinline__ float wred(float v){
#pragma unroll
    for(int o=16;o;o>>=1) v += __shfl_xor_sync(0xffffffffu, v, o);
    return v;
}

// Warp-level LayerNorm of one 256-wide row held as 8 per-lane values.
__device__ __forceinline__ void ln_store(float* dst, const float v[8],
                                         const float* __restrict__ g,
                                         const float* __restrict__ b, int lane){
    float s=0.f, ss=0.f;
#pragma unroll
    for(int i=0;i<8;i++){ s += v[i]; ss += v[i]*v[i]; }
    s  = wred(s);
    ss = wred(ss);
    float m   = s * (1.f/HH);
    float var = ss * (1.f/HH) - m*m;
    float r   = rsqrtf(var + EPSLN);
#pragma unroll
    for(int i=0;i<8;i++){
        int c = lane + 32*i;
        dst[c] = (v[i]-m)*r*g[c] + b[c];
    }
}

// Materialize the layer input x_in[8][256] into shared memory.
// l==0: embedding; l>0: LN(x2[l-1] + y[l-1]) with ln params (l-1, 2).
__device__ __forceinline__ void make_xin(float (*xs)[HH], int l,
                                         const float* __restrict__ ln_g,
                                         const float* __restrict__ ln_b){
    int w = threadIdx.x>>5, lane = threadIdx.x&31;
    if(l==0){
#pragma unroll
        for(int i=0;i<8;i++){ int c = lane+32*i; xs[w][c] = g_xe[w*HH + c]; }
    }else{
        float v[8];
#pragma unroll
        for(int i=0;i<8;i++){
            int c = lane+32*i;
            v[i] = g_x2[((l-1)*BB + w)*HH + c] + g_yb[((l-1)*BB + w)*HH + c];
        }
        ln_store(xs[w], v, ln_g + ((l-1)*3+2)*HH, ln_b + ((l-1)*3+2)*HH, lane);
    }
}

// ---------------- one-time setup kernels ----------------
// mem = embedding @ w_proj^T + b_proj        grid 32, 256thr (warp per neuron)
__global__ __launch_bounds__(256) void k_mem(const float* __restrict__ emb,
                                             const float* __restrict__ w_proj,
                                             const float* __restrict__ b_proj){
    int w = threadIdx.x>>5, lane = threadIdx.x&31;
    int j = blockIdx.x*8 + w;
    const float* wr = w_proj + (size_t)j*EE;
    float bias = b_proj[j];
    for(int b=0;b<BB;b++){
        const float* e = emb + (size_t)b*EE;
        float s=0.f;
        for(int i=lane;i<EE;i+=32) s += wr[i]*e[i];
        s = wred(s);
        if(lane==0) g_mem_[b*HH + j] = s + bias;
    }
}

// v_mem[l] = mem @ Wv_ca[l]^T + bv          grid NLL*32
__global__ __launch_bounds__(256) void k_ca1(const float* __restrict__ ca_in_w,
                                             const float* __restrict__ ca_in_b){
    int w = threadIdx.x>>5, lane = threadIdx.x&31;
    int l = blockIdx.x>>5;
    int j = (blockIdx.x&31)*8 + w;
    const float* wr = ca_in_w + ((size_t)l*3*HH + 2*HH + j)*HH;
    float bias = ca_in_b[l*3*HH + 2*HH + j];
    for(int b=0;b<BB;b++){
        const float* m = g_mem_ + b*HH;
        float s=0.f;
        for(int i=lane;i<HH;i+=32) s += wr[i]*m[i];
        s = wred(s);
        if(lane==0) g_tmpv[(l*BB+b)*HH + j] = s + bias;
    }
}

// ca_const[l] = v_mem[l] @ Wout_ca[l]^T + bout   grid NLL*32
__global__ __launch_bounds__(256) void k_ca2(const float* __restrict__ ca_out_w,
                                             const float* __restrict__ ca_out_b){
    int w = threadIdx.x>>5, lane = threadIdx.x&31;
    int l = blockIdx.x>>5;
    int j = (blockIdx.x&31)*8 + w;
    const float* wr = ca_out_w + ((size_t)l*HH + j)*HH;
    float bias = ca_out_b[l*HH + j];
    for(int b=0;b<BB;b++){
        const float* m = g_tmpv + (l*BB+b)*HH;
        float s=0.f;
        for(int i=lane;i<HH;i+=32) s += wr[i]*m[i];
        s = wred(s);
        if(lane==0) g_ca[(l*BB+b)*HH + j] = s + bias;
    }
}

// initial embedding (BOS) + pos 0; reset argmax     grid 1, 256thr
__global__ __launch_bounds__(256) void k_init(const float* __restrict__ tok_emb,
                                              const float* __restrict__ pos_enc){
    int w = threadIdx.x>>5, lane = threadIdx.x&31;
    const float* te = tok_emb + (size_t)BOSTOK*HH;
#pragma unroll
    for(int i=0;i<8;i++){ int c = lane+32*i; g_xe[w*HH + c] = te[c] + pos_enc[c]; }
    if(lane==0) g_am[w] = 0ull;
}

// ---------------- per-step kernels ----------------
// QKV GEMV, writes q / K-cache / V-cache at position t.   grid 96
__global__ __launch_bounds__(256) void k_qkv(const float* __restrict__ sa_in_w,
                                             const float* __restrict__ sa_in_b,
                                             const float* __restrict__ ln_g,
                                             const float* __restrict__ ln_b,
                                             int l, int t){
    __shared__ float xs[BB][HH];
    make_xin(xs, l, ln_g, ln_b);
    __syncthreads();
    int w = threadIdx.x>>5, lane = threadIdx.x&31;
    int j = blockIdx.x*8 + w;                 // 0..767
    const float* wr = sa_in_w + ((size_t)l*3*HH + j)*HH;
    float wreg[8];
#pragma unroll
    for(int i=0;i<8;i++) wreg[i] = wr[lane+32*i];
    float bias = sa_in_b[l*3*HH + j];
#pragma unroll
    for(int b=0;b<BB;b++){
        float s=0.f;
#pragma unroll
        for(int i=0;i<8;i++) s += wreg[i]*xs[b][lane+32*i];
        s = wred(s);
        if(lane==0){
            s += bias;
            if(j < HH)        g_q [b*HH + j] = s;
            else if(j < 2*HH) g_Kc[((size_t)(l*BB+b)*LL + t)*HH + (j-HH)]   = s;
            else              g_Vc[((size_t)(l*BB+b)*LL + t)*HH + (j-2*HH)] = s;
        }
    }
}

// Fused attention + out-projection. grid 8 (block = batch).
// Phase 1: warp = head, compute attention output into shared.
// Phase 2: 8 warps compute the 256 out-proj outputs (warp strides by 8).
__global__ __launch_bounds__(256) void k_attnproj(const float* __restrict__ sa_out_w,
                                                  const float* __restrict__ sa_out_b,
                                                  int l, int t){
    int b = blockIdx.x, w = threadIdx.x>>5, lane = threadIdx.x&31;
    __shared__ float sc[NHH][LL+2];
    __shared__ float ao[HH];
    int n = t+1;
    float q = g_q[b*HH + w*HDD + lane];
    const float* Kb = g_Kc + (size_t)(l*BB+b)*LL*HH + w*HDD + lane;
    for(int i=0;i<n;i++){
        float s = q * Kb[(size_t)i*HH];
        s = wred(s);
        if(lane==0) sc[w][i] = s * 0.17677669529663688f;   // 1/sqrt(32)
    }
    __syncwarp();
    float mx = -1e30f;
    for(int i=0;i<n;i++) mx = fmaxf(mx, sc[w][i]);
    float sum = 0.f;
    for(int i=0;i<n;i++) sum += expf(sc[w][i]-mx);
    const float* Vb = g_Vc + (size_t)(l*BB+b)*LL*HH + w*HDD + lane;
    float o = 0.f;
    for(int i=0;i<n;i++) o += expf(sc[w][i]-mx) * Vb[(size_t)i*HH];
    ao[w*HDD + lane] = o / sum;
    __syncthreads();
    // Phase 2: out-projection, warp w handles rows j = w, w+8, ...
    for(int j=w; j<HH; j+=8){
        const float* wr = sa_out_w + ((size_t)l*HH + j)*HH;
        float s=0.f;
#pragma unroll
        for(int i=0;i<8;i++) s += wr[lane+32*i]*ao[lane+32*i];
        s = wred(s);
        if(lane==0) g_pr[b*HH + j] = s + sa_out_b[l*HH + j];
    }
}

// x2 = LN(LN(xin + proj) + ca_const); h = relu(x2 @ W1^T + b1)     grid 256
__global__ __launch_bounds__(256) void k_ff1(const float* __restrict__ ff1_w,
                                             const float* __restrict__ ff1_b,
                                             const float* __restrict__ ln_g,
                                             const float* __restrict__ ln_b,
                                             int l){
    __shared__ float xs[BB][HH];
    int w = threadIdx.x>>5, lane = threadIdx.x&31;
    make_xin(xs, l, ln_g, ln_b);
    {   // chain the two LNs in place (warp owns its row)
        float v[8];
#pragma unroll
        for(int i=0;i<8;i++){ int c=lane+32*i; v[i] = xs[w][c] + g_pr[w*HH + c]; }
        ln_store(xs[w], v, ln_g + (l*3+0)*HH, ln_b + (l*3+0)*HH, lane);
#pragma unroll
        for(int i=0;i<8;i++){ int c=lane+32*i; v[i] = xs[w][c] + g_ca[(l*BB+w)*HH + c]; }
        ln_store(xs[w], v, ln_g + (l*3+1)*HH, ln_b + (l*3+1)*HH, lane);
        if(blockIdx.x==0){
#pragma unroll
            for(int i=0;i<8;i++){ int c=lane+32*i; g_x2[(l*BB+w)*HH + c] = xs[w][c]; }
        }
    }
    __syncthreads();
    int j = blockIdx.x*8 + w;                 // 0..2047
    const float* wr = ff1_w + ((size_t)l*FFF + j)*HH;
    float wreg[8];
#pragma unroll
    for(int i=0;i<8;i++) wreg[i] = wr[lane+32*i];
    float bias = ff1_b[l*FFF + j];
#pragma unroll
    for(int b=0;b<BB;b++){
        float s=0.f;
#pragma unroll
        for(int i=0;i<8;i++) s += wreg[i]*xs[b][lane+32*i];
        s = wred(s);
        if(lane==0) g_hbuf[b*FFF + j] = fmaxf(s + bias, 0.f);
    }
}

// y = h @ W2^T + b2        grid 32 (K chunked through smem)
__global__ __launch_bounds__(256) void k_ff2(const float* __restrict__ ff2_w,
                                             const float* __restrict__ ff2_b,
                                             int l){
    __shared__ float hs[BB][512];
    int w = threadIdx.x>>5, lane = threadIdx.x&31;
    int j = blockIdx.x*8 + w;
    const float* wr = ff2_w + ((size_t)l*HH + j)*FFF;
    float acc[BB];
#pragma unroll
    for(int b=0;b<BB;b++) acc[b]=0.f;
    for(int c=0;c<4;c++){
        __syncthreads();
        for(int i=threadIdx.x;i<BB*512;i+=256)
            hs[i>>9][i&511] = g_hbuf[(i>>9)*FFF + c*512 + (i&511)];
        __syncthreads();
        float wreg[16];
#pragma unroll
        for(int i=0;i<16;i++) wreg[i] = wr[c*512 + lane + 32*i];
#pragma unroll
        for(int b=0;b<BB;b++){
            float s=0.f;
#pragma unroll
            for(int i=0;i<16;i++) s += wreg[i]*hs[b][lane+32*i];
            acc[b] += s;
        }
    }
    float bias = ff2_b[l*HH + j];
#pragma unroll
    for(int b=0;b<BB;b++){
        float s = wred(acc[b]);
        if(lane==0) g_yb[(l*BB+b)*HH + j] = s + bias;
    }
}

// logits = LN(x2[3]+y[3]) @ fc^T + b, write output, fused argmax.  grid 6283
__global__ __launch_bounds__(256) void k_fc(const float* __restrict__ fc_w,
                                            const float* __restrict__ fc_b,
                                            const float* __restrict__ ln_g,
                                            const float* __restrict__ ln_b,
                                            float* __restrict__ out, int t){
    __shared__ float hs[BB][HH];
    __shared__ unsigned long long kk[8][BB];
    int w = threadIdx.x>>5, lane = threadIdx.x&31;
    {
        float v[8];
#pragma unroll
        for(int i=0;i<8;i++){
            int c = lane+32*i;
            v[i] = g_x2[(3*BB+w)*HH + c] + g_yb[(3*BB+w)*HH + c];
        }
        ln_store(hs[w], v, ln_g + (3*3+2)*HH, ln_b + (3*3+2)*HH, lane);
    }
    __syncthreads();
    int j = blockIdx.x*8 + w;
    if(j < VV){
        const float* wr = fc_w + (size_t)j*HH;
        float wreg[8];
#pragma unroll
        for(int i=0;i<8;i++) wreg[i] = wr[lane+32*i];
        float bias = fc_b[j];
#pragma unroll
        for(int b=0;b<BB;b++){
            float s=0.f;
#pragma unroll
            for(int i=0;i<8;i++) s += wreg[i]*hs[b][lane+32*i];
            s = wred(s);
            if(lane==0){
                s += bias;
                out[((size_t)b*STEPS + t)*VV + j] = s;
                unsigned int fb = __float_as_uint(s);
                fb = (fb & 0x80000000u) ? ~fb : (fb | 0x80000000u);
                kk[w][b] = ((unsigned long long)fb << 32) | (unsigned)(0x7FFFFFFFu - j);
            }
        }
    }else if(lane==0){
        for(int b=0;b<BB;b++) kk[w][b] = 0ull;
    }
    __syncthreads();
    if(threadIdx.x < BB){
        int b = threadIdx.x;
        unsigned long long best = 0ull;
#pragma unroll
        for(int ww=0; ww<8; ww++){ unsigned long long k = kk[ww][b]; if(k>best) best=k; }
        unsigned long long cur = *(volatile unsigned long long*)&g_am[b];
        if(best > cur) atomicMax(&g_am[b], best);
    }
}

// read argmax -> next-token embedding; reset argmax.   grid 1
__global__ __launch_bounds__(256) void k_fin(const float* __restrict__ tok_emb,
                                             const float* __restrict__ pos_enc,
                                             int t){
    int w = threadIdx.x>>5, lane = threadIdx.x&31;
    unsigned long long key = g_am[w];
    int tok = (int)(0x7FFFFFFFu - (unsigned)(key & 0xFFFFFFFFull));
    const float* te = tok_emb + (size_t)tok*HH;
    const float* pe = pos_enc + (size_t)(t+1)*HH;
#pragma unroll
    for(int i=0;i<8;i++){ int c = lane+32*i; g_xe[w*HH + c] = te[c] + pe[c]; }
    if(lane==0) g_am[w] = 0ull;
}

// ---------------- launch ----------------
extern "C" void kernel_launch(void* const* d_in, const int* in_sizes, int n_in,
                              void* d_out, int out_size){
    const float* embedding = (const float*)d_in[0];
    const float* w_proj    = (const float*)d_in[1];
    const float* b_proj    = (const float*)d_in[2];
    const float* tok_emb   = (const float*)d_in[3];
    const float* pos_enc   = (const float*)d_in[4];
    const float* sa_in_w   = (const float*)d_in[5];
    const float* sa_in_b   = (const float*)d_in[6];
    const float* sa_out_w  = (const float*)d_in[7];
    const float* sa_out_b  = (const float*)d_in[8];
    const float* ca_in_w   = (const float*)d_in[9];
    const float* ca_in_b   = (const float*)d_in[10];
    const float* ca_out_w  = (const float*)d_in[11];
    const float* ca_out_b  = (const float*)d_in[12];
    const float* ff1_w     = (const float*)d_in[13];
    const float* ff1_b     = (const float*)d_in[14];
    const float* ff2_w     = (const float*)d_in[15];
    const float* ff2_b     = (const float*)d_in[16];
    const float* ln_g      = (const float*)d_in[17];
    const float* ln_b      = (const float*)d_in[18];
    const float* fc_w      = (const float*)d_in[19];
    const float* fc_b      = (const float*)d_in[20];
    float* out = (float*)d_out;

    k_mem <<<32, 256>>>(embedding, w_proj, b_proj);
    k_ca1 <<<NLL*32, 256>>>(ca_in_w, ca_in_b);
    k_ca2 <<<NLL*32, 256>>>(ca_out_w, ca_out_b);
    k_init<<<1, 256>>>(tok_emb, pos_enc);

    for(int t=0; t<STEPS; t++){
        for(int l=0; l<NLL; l++){
            k_qkv     <<<96, 256>>>(sa_in_w, sa_in_b, ln_g, ln_b, l, t);
            k_attnproj<<<BB, 256>>>(sa_out_w, sa_out_b, l, t);
            k_ff1     <<<256,256>>>(ff1_w, ff1_b, ln_g, ln_b, l);
            k_ff2     <<<32, 256>>>(ff2_w, ff2_b, l);
        }
        k_fc <<<(VV+7)/8, 256>>>(fc_w, fc_b, ln_g, ln_b, out, t);
        k_fin<<<1, 256>>>(tok_emb, pos_enc, t);
    }
}

// round 4
// speedup vs baseline: 1.1145x; 1.1145x over previous
#include <cuda_runtime.h>
#include <cstdint>
#include <cstddef>

// Problem constants
#define BB   8
#define HH   256
#define NHH  8
#define HDD  32
#define LL   50
#define VV   50257
#define NLL  4
#define FFF  2048
#define EE   1536
#define BOSTOK 50256
#define STEPS 49
#define EPSLN 1e-5f

// Persistent-kernel config
#define NB   128     // blocks (<= SM count -> co-resident, barrier is safe)
#define NT   256     // threads per block (8 warps)
#define RPB  393     // FC rows per block: 128*393 = 50304 >= VV

// ---------------- device scratch (no allocations allowed) ----------------
__device__ float g_mem_[BB*HH];                 // projected memory [B,H]
__device__ float g_tmpv[NLL*BB*HH];             // v_mem per layer
__device__ float g_ca  [NLL*BB*HH];             // cross-attn constant per layer
__device__ float g_q   [BB*HH];                 // q of current layer
__device__ float g_Kc  [NLL*BB*LL*HH];          // K cache
__device__ float g_Vc  [NLL*BB*LL*HH];          // V cache
__device__ float g_pr  [BB*HH];                 // attn out-proj output
__device__ float g_x2  [NLL*BB*HH];             // x2 (post-LN2) per layer
__device__ float g_yb  [NLL*BB*HH];             // FFN output per layer
__device__ float g_hbuf[BB*FFF];                // FFN hidden
__device__ unsigned long long g_am[BB];         // packed argmax (val<<32 | inv idx)
__device__ int g_tok[BB];                       // current step token per batch
__device__ unsigned g_cnt;                      // grid barrier arrive count
__device__ unsigned g_gen;                      // grid barrier generation

// ---------------- helpers ----------------
__device__ __forceinline__ float wred(float v){
#pragma unroll
    for(int o=16;o;o>>=1) v += __shfl_xor_sync(0xffffffffu, v, o);
    return v;
}
__device__ __forceinline__ float wredmax(float v){
#pragma unroll
    for(int o=16;o;o>>=1) v = fmaxf(v, __shfl_xor_sync(0xffffffffu, v, o));
    return v;
}

// Reduce 8 per-lane partial sums (indexed by batch) across the warp in 9 shfls.
// Result: every lane of 4-lane group g holds the total for batch
// bmap = 4*bit4(lane) + 2*bit3(lane) + bit2(lane).
__device__ __forceinline__ float red8(float a[8], int lane){
#pragma unroll
    for(int b=0;b<4;b++){
        float send = (lane&16)? a[b] : a[b+4];
        float got  = __shfl_xor_sync(0xffffffffu, send, 16);
        a[b] = ((lane&16)? a[b+4] : a[b]) + got;
    }
#pragma unroll
    for(int b=0;b<2;b++){
        float send = (lane&8)? a[b] : a[b+2];
        float got  = __shfl_xor_sync(0xffffffffu, send, 8);
        a[b] = ((lane&8)? a[b+2] : a[b]) + got;
    }
    {
        float send = (lane&4)? a[0] : a[1];
        float got  = __shfl_xor_sync(0xffffffffu, send, 4);
        a[0] = ((lane&4)? a[1] : a[0]) + got;
    }
    a[0] += __shfl_xor_sync(0xffffffffu, a[0], 2);
    a[0] += __shfl_xor_sync(0xffffffffu, a[0], 1);
    return a[0];
}

// Grid-wide barrier. All NB blocks co-resident -> safe. Generation compare is
// by inequality so state is replay-safe and wrap-safe.
__device__ __forceinline__ void gbar(){
    __syncthreads();
    if(threadIdx.x==0){
        volatile unsigned* vg = (volatile unsigned*)&g_gen;
        unsigned gen = *vg;
        __threadfence();
        unsigned a = atomicAdd(&g_cnt, 1u);
        if(a == NB-1u){
            *(volatile unsigned*)&g_cnt = 0u;
            __threadfence();
            atomicAdd(&g_gen, 1u);
        }else{
            while(*vg == gen){ __nanosleep(32); }
        }
        __threadfence();
    }
    __syncthreads();
}

// In-place warp LayerNorm of one 256-wide row held as 8 per-lane values.
__device__ __forceinline__ void ln_reg(float v[8], const float* __restrict__ g,
                                       const float* __restrict__ b, int lane){
    float s=0.f, ss=0.f;
#pragma unroll
    for(int i=0;i<8;i++){ s += v[i]; ss += v[i]*v[i]; }
    s  = wred(s);
    ss = wred(ss);
    float m   = s * (1.f/HH);
    float var = ss * (1.f/HH) - m*m;
    float r   = rsqrtf(var + EPSLN);
#pragma unroll
    for(int i=0;i<8;i++){
        int c = lane + 32*i;
        v[i] = (v[i]-m)*r*g[c] + b[c];
    }
}

struct __align__(16) SMem {
    float xs[BB][HH];                            // 8KB: layer input / fc hidden
    union {
        struct { float qs[HH]; float ps[NHH][64]; float ao[HH]; } at;   // attn
        float h2[BB][512];                       // 16KB: ff2 staging
        struct { float logit[BB][400]; unsigned long long wb[64]; } fc; // fc
    } u;
};

__global__ void __launch_bounds__(NT, 1)
mega(const float* __restrict__ embedding, const float* __restrict__ w_proj,
     const float* __restrict__ b_proj,    const float* __restrict__ tok_emb,
     const float* __restrict__ pos_enc,   const float* __restrict__ sa_in_w,
     const float* __restrict__ sa_in_b,   const float* __restrict__ sa_out_w,
     const float* __restrict__ sa_out_b,  const float* __restrict__ ca_in_w,
     const float* __restrict__ ca_in_b,   const float* __restrict__ ca_out_w,
     const float* __restrict__ ca_out_b,  const float* __restrict__ ff1_w,
     const float* __restrict__ ff1_b,     const float* __restrict__ ff2_w,
     const float* __restrict__ ff2_b,     const float* __restrict__ ln_g,
     const float* __restrict__ ln_b,      const float* __restrict__ fc_w,
     const float* __restrict__ fc_b,      float* __restrict__ out)
{
    __shared__ SMem sm;
    const int tid  = threadIdx.x;
    const int w    = tid >> 5;
    const int lane = tid & 31;
    const int bl   = blockIdx.x;
    const int gw   = bl*8 + w;                  // global warp id 0..1023
    const int bmap = ((lane>>4)&1)*4 + ((lane>>3)&1)*2 + ((lane>>2)&1);
    const bool is4 = (lane&3)==0;

    // ================= setup =================
    // S1: mem = embedding @ w_proj^T + b_proj   (256 rows, warps 0..255)
    if(gw < HH){
        int j = gw;
        const float* wr = w_proj + (size_t)j*EE;
        float acc[8];
#pragma unroll
        for(int b=0;b<BB;b++) acc[b]=0.f;
        for(int i=lane;i<EE;i+=32){
            float wv = wr[i];
#pragma unroll
            for(int b=0;b<BB;b++) acc[b] += wv*embedding[b*EE+i];
        }
        float tot = red8(acc, lane);
        if(is4) g_mem_[bmap*HH + j] = tot + b_proj[j];
    }
    gbar();
    // S2: v_mem[l] = mem @ Wv_ca[l]^T + bv   (1024 warp-tasks)
    {
        int l = gw>>8, j = gw&255;
        const float* wr = ca_in_w + ((size_t)l*3*HH + 2*HH + j)*HH;
        float acc[8];
#pragma unroll
        for(int b=0;b<BB;b++) acc[b]=0.f;
#pragma unroll
        for(int k=0;k<8;k++){
            int i = lane + 32*k;
            float wv = wr[i];
#pragma unroll
            for(int b=0;b<BB;b++) acc[b] += wv*g_mem_[b*HH+i];
        }
        float tot = red8(acc, lane);
        if(is4) g_tmpv[(l*BB+bmap)*HH + j] = tot + ca_in_b[l*3*HH + 2*HH + j];
    }
    gbar();
    // S3: ca_const[l] = v_mem[l] @ Wout_ca[l]^T + bout
    {
        int l = gw>>8, j = gw&255;
        const float* wr = ca_out_w + ((size_t)l*HH + j)*HH;
        float acc[8];
#pragma unroll
        for(int b=0;b<BB;b++) acc[b]=0.f;
#pragma unroll
        for(int k=0;k<8;k++){
            int i = lane + 32*k;
            float wv = wr[i];
#pragma unroll
            for(int b=0;b<BB;b++) acc[b] += wv*g_tmpv[(l*BB+b)*HH+i];
        }
        float tot = red8(acc, lane);
        if(is4) g_ca[(l*BB+bmap)*HH + j] = tot + ca_out_b[l*HH + j];
    }
    gbar();

    // ================= decode steps =================
    for(int t=0; t<STEPS; t++){
        for(int l=0; l<NLL; l++){
            // ---- phase QKV: stage layer input, then 768-row GEMV ----
            {
                // warp w stages batch-w row of layer input into sm.xs
                if(l==0){
                    int tok = (t==0) ? BOSTOK
                        : (int)(0x7FFFFFFFu - (unsigned)(g_am[w] & 0xFFFFFFFFull));
                    if(bl==0 && lane==0) g_tok[w] = tok;
                    const float* te = tok_emb + (size_t)tok*HH;
                    const float* pe = pos_enc + (size_t)t*HH;
#pragma unroll
                    for(int i=0;i<8;i++){ int c=lane+32*i; sm.xs[w][c] = te[c]+pe[c]; }
                }else{
                    float v[8];
#pragma unroll
                    for(int i=0;i<8;i++){
                        int c=lane+32*i;
                        v[i] = g_x2[((l-1)*BB+w)*HH+c] + g_yb[((l-1)*BB+w)*HH+c];
                    }
                    ln_reg(v, ln_g+((l-1)*3+2)*HH, ln_b+((l-1)*3+2)*HH, lane);
#pragma unroll
                    for(int i=0;i<8;i++) sm.xs[w][lane+32*i] = v[i];
                }
                __syncthreads();
                if(gw < 3*HH){
                    int j = gw;
                    const float* wr = sa_in_w + ((size_t)l*3*HH + j)*HH;
                    float wreg[8];
#pragma unroll
                    for(int i=0;i<8;i++) wreg[i] = wr[lane+32*i];
                    float acc[8];
#pragma unroll
                    for(int b=0;b<BB;b++){
                        float s=0.f;
#pragma unroll
                        for(int i=0;i<8;i++) s += wreg[i]*sm.xs[b][lane+32*i];
                        acc[b]=s;
                    }
                    float tot = red8(acc, lane);
                    if(is4){
                        float s = tot + sa_in_b[l*3*HH + j];
                        int b = bmap;
                        if(j < HH)        g_q [b*HH + j] = s;
                        else if(j < 2*HH) g_Kc[((size_t)(l*BB+b)*LL + t)*HH + (j-HH)]   = s;
                        else              g_Vc[((size_t)(l*BB+b)*LL + t)*HH + (j-2*HH)] = s;
                    }
                }
            }
            gbar();
            // ---- phase ATTN + out-projection (blocks 0..7, block = batch) ----
            if(bl < BB){
                int b = bl, n = t+1, h = w;
                sm.u.at.qs[h*32+lane] = g_q[b*HH + h*32 + lane];
                __syncwarp();
                const float* Kb = g_Kc + ((size_t)(l*BB+b)*LL)*HH + h*HDD;
                float sc0=-1e30f, sc1=-1e30f;
                int i0=lane, i1=lane+32;
                if(i0<n){
                    const float4* kr = (const float4*)(Kb + (size_t)i0*HH);
                    float s=0.f;
#pragma unroll
                    for(int r=0;r<8;r++){
                        float4 kv = kr[r];
                        s += kv.x*sm.u.at.qs[h*32+4*r+0] + kv.y*sm.u.at.qs[h*32+4*r+1]
                           + kv.z*sm.u.at.qs[h*32+4*r+2] + kv.w*sm.u.at.qs[h*32+4*r+3];
                    }
                    sc0 = s * 0.17677669529663688f;
                }
                if(i1<n){
                    const float4* kr = (const float4*)(Kb + (size_t)i1*HH);
                    float s=0.f;
#pragma unroll
                    for(int r=0;r<8;r++){
                        float4 kv = kr[r];
                        s += kv.x*sm.u.at.qs[h*32+4*r+0] + kv.y*sm.u.at.qs[h*32+4*r+1]
                           + kv.z*sm.u.at.qs[h*32+4*r+2] + kv.w*sm.u.at.qs[h*32+4*r+3];
                    }
                    sc1 = s * 0.17677669529663688f;
                }
                float mx = wredmax(fmaxf(sc0, sc1));
                float p0 = (i0<n)? expf(sc0-mx) : 0.f;
                float p1 = (i1<n)? expf(sc1-mx) : 0.f;
                float sum = wred(p0+p1);
                sm.u.at.ps[h][lane]    = p0;
                sm.u.at.ps[h][lane+32] = p1;
                __syncwarp();
                const float* Vb = g_Vc + ((size_t)(l*BB+b)*LL)*HH + h*HDD;
                float o=0.f;
                for(int i=0;i<n;i++) o += sm.u.at.ps[h][i] * Vb[(size_t)i*HH + lane];
                sm.u.at.ao[h*HDD + lane] = o / sum;
                __syncthreads();
                // out-projection: warp w handles rows j = w, w+8, ...
                for(int j=w; j<HH; j+=8){
                    const float* wr = sa_out_w + ((size_t)l*HH + j)*HH;
                    float s=0.f;
#pragma unroll
                    for(int i=0;i<8;i++) s += wr[lane+32*i]*sm.u.at.ao[lane+32*i];
                    s = wred(s);
                    if(lane==0) g_pr[b*HH + j] = s + sa_out_b[l*HH + j];
                }
            }else if(bl==BB && l==0){
                if(tid < BB) g_am[tid] = 0ull;   // reset for this step's FC
            }
            gbar();
            // ---- phase FF1: chained LNs -> x2, then 2048-row GEMV + relu ----
            {
                float v[8];
                if(l==0){
                    int tok = g_tok[w];
                    const float* te = tok_emb + (size_t)tok*HH;
                    const float* pe = pos_enc + (size_t)t*HH;
#pragma unroll
                    for(int i=0;i<8;i++){ int c=lane+32*i; v[i] = te[c]+pe[c]; }
                }else{
#pragma unroll
                    for(int i=0;i<8;i++){
                        int c=lane+32*i;
                        v[i] = g_x2[((l-1)*BB+w)*HH+c] + g_yb[((l-1)*BB+w)*HH+c];
                    }
                    ln_reg(v, ln_g+((l-1)*3+2)*HH, ln_b+((l-1)*3+2)*HH, lane);
                }
#pragma unroll
                for(int i=0;i<8;i++) v[i] += g_pr[w*HH + lane+32*i];
                ln_reg(v, ln_g+(l*3+0)*HH, ln_b+(l*3+0)*HH, lane);
#pragma unroll
                for(int i=0;i<8;i++) v[i] += g_ca[(l*BB+w)*HH + lane+32*i];
                ln_reg(v, ln_g+(l*3+1)*HH, ln_b+(l*3+1)*HH, lane);
#pragma unroll
                for(int i=0;i<8;i++) sm.xs[w][lane+32*i] = v[i];
                if(bl==0){
#pragma unroll
                    for(int i=0;i<8;i++) g_x2[(l*BB+w)*HH + lane+32*i] = v[i];
                }
                __syncthreads();
#pragma unroll
                for(int rr=0; rr<2; rr++){
                    int j = gw + rr*1024;
                    const float* wr = ff1_w + ((size_t)l*FFF + j)*HH;
                    float wreg[8];
#pragma unroll
                    for(int i=0;i<8;i++) wreg[i] = wr[lane+32*i];
                    float acc[8];
#pragma unroll
                    for(int b=0;b<BB;b++){
                        float s=0.f;
#pragma unroll
                        for(int i=0;i<8;i++) s += wreg[i]*sm.xs[b][lane+32*i];
                        acc[b]=s;
                    }
                    float tot = red8(acc, lane);
                    if(is4) g_hbuf[bmap*FFF + j] = fmaxf(tot + ff1_b[l*FFF + j], 0.f);
                }
            }
            gbar();
            // ---- phase FF2 (blocks 0..31): 256-row GEMV over 2048 ----
            if(bl < 32){
                int j = bl*8 + w;
                const float* wr = ff2_w + ((size_t)l*HH + j)*FFF;
                float acc[8];
#pragma unroll
                for(int b=0;b<BB;b++) acc[b]=0.f;
                for(int c=0;c<4;c++){
                    __syncthreads();
                    for(int i=tid;i<BB*512;i+=NT)
                        sm.u.h2[i>>9][i&511] = g_hbuf[(i>>9)*FFF + c*512 + (i&511)];
                    __syncthreads();
                    float wreg[16];
#pragma unroll
                    for(int i=0;i<16;i++) wreg[i] = wr[c*512 + lane + 32*i];
#pragma unroll
                    for(int b=0;b<BB;b++){
                        float s=0.f;
#pragma unroll
                        for(int i=0;i<16;i++) s += wreg[i]*sm.u.h2[b][lane+32*i];
                        acc[b] += s;
                    }
                }
                float tot = red8(acc, lane);
                if(is4) g_yb[(l*BB+bmap)*HH + j] = tot + ff2_b[l*HH + j];
            }
            gbar();
        } // layers

        // ---- phase FC: logits + argmax ----
        {
            float v[8];
#pragma unroll
            for(int i=0;i<8;i++){
                int c=lane+32*i;
                v[i] = g_x2[(3*BB+w)*HH+c] + g_yb[(3*BB+w)*HH+c];
            }
            ln_reg(v, ln_g+(3*3+2)*HH, ln_b+(3*3+2)*HH, lane);
#pragma unroll
            for(int i=0;i<8;i++) sm.xs[w][lane+32*i] = v[i];
            __syncthreads();

            // cache activations in registers (lane owns cols 4L..4L+3, 128+4L..)
            float4 xr[BB][2];
#pragma unroll
            for(int b=0;b<BB;b++){
                const float4* xp = (const float4*)sm.xs[b];
                xr[b][0] = xp[lane];
                xr[b][1] = xp[lane+32];
            }
            int base  = bl*RPB;
            int nrows = VV - base; if(nrows > RPB) nrows = RPB;
            unsigned long long best = 0ull;
            for(int r=w; r<RPB; r+=8){
                int j = base + r;
                if(j < VV){
                    const float4* wr4 = (const float4*)(fc_w + (size_t)j*HH);
                    float4 w0 = wr4[lane], w1 = wr4[lane+32];
                    float acc[8];
#pragma unroll
                    for(int b=0;b<BB;b++){
                        float4 x0 = xr[b][0], x1 = xr[b][1];
                        acc[b] = w0.x*x0.x + w0.y*x0.y + w0.z*x0.z + w0.w*x0.w
                               + w1.x*x1.x + w1.y*x1.y + w1.z*x1.z + w1.w*x1.w;
                    }
                    float tot = red8(acc, lane);
                    if(is4){
                        float s = tot + fc_b[j];
                        sm.u.fc.logit[bmap][r] = s;
                        unsigned fb = __float_as_uint(s);
                        fb = (fb & 0x80000000u) ? ~fb : (fb | 0x80000000u);
                        unsigned long long key =
                            ((unsigned long long)fb << 32) | (unsigned)(0x7FFFFFFFu - j);
                        if(key > best) best = key;
                    }
                }
            }
            if(is4) sm.u.fc.wb[w*8 + bmap] = best;
            __syncthreads();
            if(tid < BB){
                unsigned long long bb = 0ull;
#pragma unroll
                for(int ww=0; ww<8; ww++){
                    unsigned long long k = sm.u.fc.wb[ww*8 + tid];
                    if(k > bb) bb = k;
                }
                atomicMax(&g_am[tid], bb);
            }
            // coalesced logit writeback
            for(int b=0;b<BB;b++){
                float* op = out + ((size_t)b*STEPS + t)*VV + base;
                for(int rr=tid; rr<nrows; rr+=NT) op[rr] = sm.u.fc.logit[b][rr];
            }
        }
        gbar();
    } // steps
}

// ---------------- launch ----------------
extern "C" void kernel_launch(void* const* d_in, const int* in_sizes, int n_in,
                              void* d_out, int out_size){
    const float* embedding = (const float*)d_in[0];
    const float* w_proj    = (const float*)d_in[1];
    const float* b_proj    = (const float*)d_in[2];
    const float* tok_emb   = (const float*)d_in[3];
    const float* pos_enc   = (const float*)d_in[4];
    const float* sa_in_w   = (const float*)d_in[5];
    const float* sa_in_b   = (const float*)d_in[6];
    const float* sa_out_w  = (const float*)d_in[7];
    const float* sa_out_b  = (const float*)d_in[8];
    const float* ca_in_w   = (const float*)d_in[9];
    const float* ca_in_b   = (const float*)d_in[10];
    const float* ca_out_w  = (const float*)d_in[11];
    const float* ca_out_b  = (const float*)d_in[12];
    const float* ff1_w     = (const float*)d_in[13];
    const float* ff1_b     = (const float*)d_in[14];
    const float* ff2_w     = (const float*)d_in[15];
    const float* ff2_b     = (const float*)d_in[16];
    const float* ln_g      = (const float*)d_in[17];
    const float* ln_b      = (const float*)d_in[18];
    const float* fc_w      = (const float*)d_in[19];
    const float* fc_b      = (const float*)d_in[20];
    float* out = (float*)d_out;

    mega<<<NB, NT>>>(embedding, w_proj, b_proj, tok_emb, pos_enc,
                     sa_in_w, sa_in_b, sa_out_w, sa_out_b,
                     ca_in_w, ca_in_b, ca_out_w, ca_out_b,
                     ff1_w, ff1_b, ff2_w, ff2_b, ln_g, ln_b,
                     fc_w, fc_b, out);
}

// round 5
// speedup vs baseline: 1.3902x; 1.2474x over previous
#include <cuda_runtime.h>
#include <cstdint>
#include <cstddef>

// Problem constants
#define BB   8
#define HH   256
#define NHH  8
#define HDD  32
#define LL   50
#define VV   50257
#define NLL  4
#define FFF  2048
#define EE   1536
#define BOSTOK 50256
#define STEPS 49
#define EPSLN 1e-5f

// Persistent-kernel config
#define NB   128     // blocks (<= SM count -> co-resident, barrier is safe)
#define NT   512     // threads per block (16 warps)
#define NW   16      // warps per block
#define RPB  393     // FC rows per block: 128*393 = 50304 >= VV

// ---------------- device scratch (no allocations allowed) ----------------
__device__ float g_mem_[BB*HH];                 // projected memory [B,H]
__device__ float g_tmpv[NLL*BB*HH];             // v_mem per layer
__device__ float g_ca  [NLL*BB*HH];             // cross-attn constant per layer
__device__ float g_q   [BB*HH];                 // q of current layer
__device__ float g_Kc  [NLL*BB*LL*HH];          // K cache
__device__ float g_Vc  [NLL*BB*LL*HH];          // V cache
__device__ float g_pr  [BB*HH];                 // attn out-proj output
__device__ float g_x2  [NLL*BB*HH];             // x2 (post-LN2) per layer
__device__ float g_yb  [NLL*BB*HH];             // FFN output per layer
__device__ float g_hbuf[BB*FFF];                // FFN hidden
__device__ unsigned long long g_am[BB];         // packed argmax (val<<32 | inv idx)
__device__ int g_tok[BB];                       // current step token per batch
// tree barrier state: 16 group counters on separate 128B lines + root + gen
__device__ unsigned g_cntg[16*32];
__device__ unsigned g_cnt0;
__device__ unsigned g_gen;

// ---------------- helpers ----------------
__device__ __forceinline__ float wred(float v){
#pragma unroll
    for(int o=16;o;o>>=1) v += __shfl_xor_sync(0xffffffffu, v, o);
    return v;
}
__device__ __forceinline__ float wredmax(float v){
#pragma unroll
    for(int o=16;o;o>>=1) v = fmaxf(v, __shfl_xor_sync(0xffffffffu, v, o));
    return v;
}

// Reduce 8 per-lane partial sums (indexed by batch) across the warp in 9 shfls.
// Result: every lane of 4-lane group g holds the total for batch
// bmap = 4*bit4(lane) + 2*bit3(lane) + bit2(lane).
__device__ __forceinline__ float red8(float a[8], int lane){
#pragma unroll
    for(int b=0;b<4;b++){
        float send = (lane&16)? a[b] : a[b+4];
        float got  = __shfl_xor_sync(0xffffffffu, send, 16);
        a[b] = ((lane&16)? a[b+4] : a[b]) + got;
    }
#pragma unroll
    for(int b=0;b<2;b++){
        float send = (lane&8)? a[b] : a[b+2];
        float got  = __shfl_xor_sync(0xffffffffu, send, 8);
        a[b] = ((lane&8)? a[b+2] : a[b]) + got;
    }
    {
        float send = (lane&4)? a[0] : a[1];
        float got  = __shfl_xor_sync(0xffffffffu, send, 4);
        a[0] = ((lane&4)? a[1] : a[0]) + got;
    }
    a[0] += __shfl_xor_sync(0xffffffffu, a[0], 2);
    a[0] += __shfl_xor_sync(0xffffffffu, a[0], 1);
    return a[0];
}

// Grid-wide tree barrier. Arrivals: 8-way concurrency per group line, then a
// 16-way root. Generation compared by inequality -> replay/wrap safe. Counter
// resets happen before release while all other members are still spinning.
__device__ __forceinline__ void gbar(){
    __syncthreads();
    if(threadIdx.x==0){
        volatile unsigned* vg = (volatile unsigned*)&g_gen;
        unsigned gen = *vg;
        __threadfence();
        int grp = blockIdx.x >> 3;
        unsigned a = atomicAdd(&g_cntg[grp*32], 1u);
        bool released = false;
        if(a == 7u){
            *(volatile unsigned*)&g_cntg[grp*32] = 0u;
            unsigned r = atomicAdd(&g_cnt0, 1u);
            if(r == 15u){
                *(volatile unsigned*)&g_cnt0 = 0u;
                __threadfence();
                atomicAdd(&g_gen, 1u);
                released = true;
            }
        }
        if(!released){
            while(*vg == gen){ __nanosleep(32); }
        }
        __threadfence();
    }
    __syncthreads();
}

// In-place warp LayerNorm of one 256-wide row held as 8 per-lane values.
__device__ __forceinline__ void ln_reg(float v[8], const float* __restrict__ g,
                                       const float* __restrict__ b, int lane){
    float s=0.f, ss=0.f;
#pragma unroll
    for(int i=0;i<8;i++){ s += v[i]; ss += v[i]*v[i]; }
    s  = wred(s);
    ss = wred(ss);
    float m   = s * (1.f/HH);
    float var = ss * (1.f/HH) - m*m;
    float r   = rsqrtf(var + EPSLN);
#pragma unroll
    for(int i=0;i<8;i++){
        int c = lane + 32*i;
        v[i] = (v[i]-m)*r*g[c] + b[c];
    }
}

struct __align__(16) SMem {
    float xs[BB][HH];                            // 8KB: layer input / fc hidden
    union {
        struct { float qs[HH]; float ps[NHH][64]; float ao[HH]; } at;   // attn
        float h2[BB][512];                       // 16KB: ff2 staging
        struct { float logit[BB][400]; unsigned long long wb[NW*8]; } fc; // fc
    } u;
};

__global__ void __launch_bounds__(NT, 1)
mega(const float* __restrict__ embedding, const float* __restrict__ w_proj,
     const float* __restrict__ b_proj,    const float* __restrict__ tok_emb,
     const float* __restrict__ pos_enc,   const float* __restrict__ sa_in_w,
     const float* __restrict__ sa_in_b,   const float* __restrict__ sa_out_w,
     const float* __restrict__ sa_out_b,  const float* __restrict__ ca_in_w,
     const float* __restrict__ ca_in_b,   const float* __restrict__ ca_out_w,
     const float* __restrict__ ca_out_b,  const float* __restrict__ ff1_w,
     const float* __restrict__ ff1_b,     const float* __restrict__ ff2_w,
     const float* __restrict__ ff2_b,     const float* __restrict__ ln_g,
     const float* __restrict__ ln_b,      const float* __restrict__ fc_w,
     const float* __restrict__ fc_b,      float* __restrict__ out)
{
    __shared__ SMem sm;
    const int tid  = threadIdx.x;
    const int w    = tid >> 5;
    const int lane = tid & 31;
    const int bl   = blockIdx.x;
    const int gw   = bl*NW + w;                 // global warp id 0..2047
    const int bmap = ((lane>>4)&1)*4 + ((lane>>3)&1)*2 + ((lane>>2)&1);
    const bool is4 = (lane&3)==0;

    // ================= setup =================
    // S1: mem = embedding @ w_proj^T + b_proj   (256 rows)
    if(gw < HH){
        int j = gw;
        const float* wr = w_proj + (size_t)j*EE;
        float acc[8];
#pragma unroll
        for(int b=0;b<BB;b++) acc[b]=0.f;
        for(int i=lane;i<EE;i+=32){
            float wv = wr[i];
#pragma unroll
            for(int b=0;b<BB;b++) acc[b] += wv*embedding[b*EE+i];
        }
        float tot = red8(acc, lane);
        if(is4) g_mem_[bmap*HH + j] = tot + b_proj[j];
    }
    gbar();
    // S2: v_mem[l] = mem @ Wv_ca[l]^T + bv   (1024 warp-tasks)
    if(gw < NLL*HH){
        int l = gw>>8, j = gw&255;
        const float* wr = ca_in_w + ((size_t)l*3*HH + 2*HH + j)*HH;
        float acc[8];
#pragma unroll
        for(int b=0;b<BB;b++) acc[b]=0.f;
#pragma unroll
        for(int k=0;k<8;k++){
            int i = lane + 32*k;
            float wv = wr[i];
#pragma unroll
            for(int b=0;b<BB;b++) acc[b] += wv*g_mem_[b*HH+i];
        }
        float tot = red8(acc, lane);
        if(is4) g_tmpv[(l*BB+bmap)*HH + j] = tot + ca_in_b[l*3*HH + 2*HH + j];
    }
    gbar();
    // S3: ca_const[l] = v_mem[l] @ Wout_ca[l]^T + bout
    if(gw < NLL*HH){
        int l = gw>>8, j = gw&255;
        const float* wr = ca_out_w + ((size_t)l*HH + j)*HH;
        float acc[8];
#pragma unroll
        for(int b=0;b<BB;b++) acc[b]=0.f;
#pragma unroll
        for(int k=0;k<8;k++){
            int i = lane + 32*k;
            float wv = wr[i];
#pragma unroll
            for(int b=0;b<BB;b++) acc[b] += wv*g_tmpv[(l*BB+b)*HH+i];
        }
        float tot = red8(acc, lane);
        if(is4) g_ca[(l*BB+bmap)*HH + j] = tot + ca_out_b[l*HH + j];
    }
    gbar();

    // ================= decode steps =================
    for(int t=0; t<STEPS; t++){
        for(int l=0; l<NLL; l++){
            // ---- phase QKV: stage layer input, then 768-row GEMV ----
            {
                // warps 0..7 stage batch-w row of layer input into sm.xs
                if(w < BB){
                    if(l==0){
                        int tok = (t==0) ? BOSTOK
                            : (int)(0x7FFFFFFFu - (unsigned)(g_am[w] & 0xFFFFFFFFull));
                        if(bl==0 && lane==0) g_tok[w] = tok;
                        const float* te = tok_emb + (size_t)tok*HH;
                        const float* pe = pos_enc + (size_t)t*HH;
#pragma unroll
                        for(int i=0;i<8;i++){ int c=lane+32*i; sm.xs[w][c] = te[c]+pe[c]; }
                    }else{
                        float v[8];
#pragma unroll
                        for(int i=0;i<8;i++){
                            int c=lane+32*i;
                            v[i] = g_x2[((l-1)*BB+w)*HH+c] + g_yb[((l-1)*BB+w)*HH+c];
                        }
                        ln_reg(v, ln_g+((l-1)*3+2)*HH, ln_b+((l-1)*3+2)*HH, lane);
#pragma unroll
                        for(int i=0;i<8;i++) sm.xs[w][lane+32*i] = v[i];
                    }
                }
                __syncthreads();
                if(gw < 3*HH){
                    int j = gw;
                    const float* wr = sa_in_w + ((size_t)l*3*HH + j)*HH;
                    float wreg[8];
#pragma unroll
                    for(int i=0;i<8;i++) wreg[i] = wr[lane+32*i];
                    float acc[8];
#pragma unroll
                    for(int b=0;b<BB;b++){
                        float s=0.f;
#pragma unroll
                        for(int i=0;i<8;i++) s += wreg[i]*sm.xs[b][lane+32*i];
                        acc[b]=s;
                    }
                    float tot = red8(acc, lane);
                    if(is4){
                        float s = tot + sa_in_b[l*3*HH + j];
                        int b = bmap;
                        if(j < HH)        g_q [b*HH + j] = s;
                        else if(j < 2*HH) g_Kc[((size_t)(l*BB+b)*LL + t)*HH + (j-HH)]   = s;
                        else              g_Vc[((size_t)(l*BB+b)*LL + t)*HH + (j-2*HH)] = s;
                    }
                }
            }
            gbar();
            // ---- phase ATTN + out-projection (blocks 0..7, block = batch) ----
            if(bl < BB){
                int b = bl, n = t+1;
                if(w < NHH){
                    int h = w;
                    sm.u.at.qs[h*32+lane] = g_q[b*HH + h*32 + lane];
                    __syncwarp();
                    const float* Kb = g_Kc + ((size_t)(l*BB+b)*LL)*HH + h*HDD;
                    float sc0=-1e30f, sc1=-1e30f;
                    int i0=lane, i1=lane+32;
                    if(i0<n){
                        const float4* kr = (const float4*)(Kb + (size_t)i0*HH);
                        float s=0.f;
#pragma unroll
                        for(int r=0;r<8;r++){
                            float4 kv = kr[r];
                            s += kv.x*sm.u.at.qs[h*32+4*r+0] + kv.y*sm.u.at.qs[h*32+4*r+1]
                               + kv.z*sm.u.at.qs[h*32+4*r+2] + kv.w*sm.u.at.qs[h*32+4*r+3];
                        }
                        sc0 = s * 0.17677669529663688f;
                    }
                    if(i1<n){
                        const float4* kr = (const float4*)(Kb + (size_t)i1*HH);
                        float s=0.f;
#pragma unroll
                        for(int r=0;r<8;r++){
                            float4 kv = kr[r];
                            s += kv.x*sm.u.at.qs[h*32+4*r+0] + kv.y*sm.u.at.qs[h*32+4*r+1]
                               + kv.z*sm.u.at.qs[h*32+4*r+2] + kv.w*sm.u.at.qs[h*32+4*r+3];
                        }
                        sc1 = s * 0.17677669529663688f;
                    }
                    float mx = wredmax(fmaxf(sc0, sc1));
                    float p0 = (i0<n)? expf(sc0-mx) : 0.f;
                    float p1 = (i1<n)? expf(sc1-mx) : 0.f;
                    float sum = wred(p0+p1);
                    sm.u.at.ps[h][lane]    = p0;
                    sm.u.at.ps[h][lane+32] = p1;
                    __syncwarp();
                    // V accumulation, 4 independent partials -> n/4 latency chain
                    const float* Vb = g_Vc + ((size_t)(l*BB+b)*LL)*HH + h*HDD + lane;
                    float o0=0.f,o1=0.f,o2=0.f,o3=0.f;
                    int i=0;
                    for(; i+4<=n; i+=4){
                        o0 += sm.u.at.ps[h][i+0] * Vb[(size_t)(i+0)*HH];
                        o1 += sm.u.at.ps[h][i+1] * Vb[(size_t)(i+1)*HH];
                        o2 += sm.u.at.ps[h][i+2] * Vb[(size_t)(i+2)*HH];
                        o3 += sm.u.at.ps[h][i+3] * Vb[(size_t)(i+3)*HH];
                    }
                    for(; i<n; i++) o0 += sm.u.at.ps[h][i] * Vb[(size_t)i*HH];
                    sm.u.at.ao[h*HDD + lane] = ((o0+o1)+(o2+o3)) / sum;
                }
                __syncthreads();
                // out-projection: warp w handles rows j = w, w+16, ...
                for(int j=w; j<HH; j+=NW){
                    const float* wr = sa_out_w + ((size_t)l*HH + j)*HH;
                    float s=0.f;
#pragma unroll
                    for(int i=0;i<8;i++) s += wr[lane+32*i]*sm.u.at.ao[lane+32*i];
                    s = wred(s);
                    if(lane==0) g_pr[b*HH + j] = s + sa_out_b[l*HH + j];
                }
            }else if(bl==BB && l==0){
                if(tid < BB) g_am[tid] = 0ull;   // reset for this step's FC
            }
            gbar();
            // ---- phase FF1: chained LNs -> x2, then 2048-row GEMV + relu ----
            {
                if(w < BB){
                    float v[8];
                    if(l==0){
                        int tok = g_tok[w];
                        const float* te = tok_emb + (size_t)tok*HH;
                        const float* pe = pos_enc + (size_t)t*HH;
#pragma unroll
                        for(int i=0;i<8;i++){ int c=lane+32*i; v[i] = te[c]+pe[c]; }
                    }else{
#pragma unroll
                        for(int i=0;i<8;i++){
                            int c=lane+32*i;
                            v[i] = g_x2[((l-1)*BB+w)*HH+c] + g_yb[((l-1)*BB+w)*HH+c];
                        }
                        ln_reg(v, ln_g+((l-1)*3+2)*HH, ln_b+((l-1)*3+2)*HH, lane);
                    }
#pragma unroll
                    for(int i=0;i<8;i++) v[i] += g_pr[w*HH + lane+32*i];
                    ln_reg(v, ln_g+(l*3+0)*HH, ln_b+(l*3+0)*HH, lane);
#pragma unroll
                    for(int i=0;i<8;i++) v[i] += g_ca[(l*BB+w)*HH + lane+32*i];
                    ln_reg(v, ln_g+(l*3+1)*HH, ln_b+(l*3+1)*HH, lane);
#pragma unroll
                    for(int i=0;i<8;i++) sm.xs[w][lane+32*i] = v[i];
                    if(bl==0){
#pragma unroll
                        for(int i=0;i<8;i++) g_x2[(l*BB+w)*HH + lane+32*i] = v[i];
                    }
                }
                __syncthreads();
                {   // one row per warp: j = gw in 0..2047
                    int j = gw;
                    const float* wr = ff1_w + ((size_t)l*FFF + j)*HH;
                    float wreg[8];
#pragma unroll
                    for(int i=0;i<8;i++) wreg[i] = wr[lane+32*i];
                    float acc[8];
#pragma unroll
                    for(int b=0;b<BB;b++){
                        float s=0.f;
#pragma unroll
                        for(int i=0;i<8;i++) s += wreg[i]*sm.xs[b][lane+32*i];
                        acc[b]=s;
                    }
                    float tot = red8(acc, lane);
                    if(is4) g_hbuf[bmap*FFF + j] = fmaxf(tot + ff1_b[l*FFF + j], 0.f);
                }
            }
            gbar();
            // ---- phase FF2 (blocks 0..15): 256-row GEMV over 2048 ----
            if(bl < 16){
                int j = bl*NW + w;
                const float* wr = ff2_w + ((size_t)l*HH + j)*FFF;
                float acc[8];
#pragma unroll
                for(int b=0;b<BB;b++) acc[b]=0.f;
                for(int c=0;c<4;c++){
                    __syncthreads();
                    for(int i=tid;i<BB*512;i+=NT)
                        sm.u.h2[i>>9][i&511] = g_hbuf[(i>>9)*FFF + c*512 + (i&511)];
                    __syncthreads();
                    float wreg[16];
#pragma unroll
                    for(int i=0;i<16;i++) wreg[i] = wr[c*512 + lane + 32*i];
#pragma unroll
                    for(int b=0;b<BB;b++){
                        float s=0.f;
#pragma unroll
                        for(int i=0;i<16;i++) s += wreg[i]*sm.u.h2[b][lane+32*i];
                        acc[b] += s;
                    }
                }
                float tot = red8(acc, lane);
                if(is4) g_yb[(l*BB+bmap)*HH + j] = tot + ff2_b[l*HH + j];
            }
            gbar();
        } // layers

        // ---- phase FC: logits + argmax ----
        {
            if(w < BB){
                float v[8];
#pragma unroll
                for(int i=0;i<8;i++){
                    int c=lane+32*i;
                    v[i] = g_x2[(3*BB+w)*HH+c] + g_yb[(3*BB+w)*HH+c];
                }
                ln_reg(v, ln_g+(3*3+2)*HH, ln_b+(3*3+2)*HH, lane);
#pragma unroll
                for(int i=0;i<8;i++) sm.xs[w][lane+32*i] = v[i];
            }
            __syncthreads();

            // cache activations in registers (lane owns cols 4L..4L+3, 128+4L..)
            float4 xr[BB][2];
#pragma unroll
            for(int b=0;b<BB;b++){
                const float4* xp = (const float4*)sm.xs[b];
                xr[b][0] = xp[lane];
                xr[b][1] = xp[lane+32];
            }
            int base  = bl*RPB;
            int nrows = VV - base; if(nrows > RPB) nrows = RPB;
            unsigned long long best = 0ull;
            // two rows per iteration (r, r+16) -> 4 LDG.128 in flight per lane
            for(int r=w; r<RPB; r+=2*NW){
                int ja = base + r;
                int rb = r + NW;
                int jb = base + rb;
                bool va = (ja < VV), vb = (rb < RPB) && (jb < VV);
                float4 wa0, wa1, wb0, wb1;
                if(va){
                    const float4* wr4 = (const float4*)(fc_w + (size_t)ja*HH);
                    wa0 = wr4[lane]; wa1 = wr4[lane+32];
                }
                if(vb){
                    const float4* wr4 = (const float4*)(fc_w + (size_t)jb*HH);
                    wb0 = wr4[lane]; wb1 = wr4[lane+32];
                }
                if(va){
                    float acc[8];
#pragma unroll
                    for(int b=0;b<BB;b++){
                        float4 x0 = xr[b][0], x1 = xr[b][1];
                        acc[b] = wa0.x*x0.x + wa0.y*x0.y + wa0.z*x0.z + wa0.w*x0.w
                               + wa1.x*x1.x + wa1.y*x1.y + wa1.z*x1.z + wa1.w*x1.w;
                    }
                    float tot = red8(acc, lane);
                    if(is4){
                        float s = tot + fc_b[ja];
                        sm.u.fc.logit[bmap][r] = s;
                        unsigned fb = __float_as_uint(s);
                        fb = (fb & 0x80000000u) ? ~fb : (fb | 0x80000000u);
                        unsigned long long key =
                            ((unsigned long long)fb << 32) | (unsigned)(0x7FFFFFFFu - ja);
                        if(key > best) best = key;
                    }
                }
                if(vb){
                    float acc[8];
#pragma unroll
                    for(int b=0;b<BB;b++){
                        float4 x0 = xr[b][0], x1 = xr[b][1];
                        acc[b] = wb0.x*x0.x + wb0.y*x0.y + wb0.z*x0.z + wb0.w*x0.w
                               + wb1.x*x1.x + wb1.y*x1.y + wb1.z*x1.z + wb1.w*x1.w;
                    }
                    float tot = red8(acc, lane);
                    if(is4){
                        float s = tot + fc_b[jb];
                        sm.u.fc.logit[bmap][rb] = s;
                        unsigned fb = __float_as_uint(s);
                        fb = (fb & 0x80000000u) ? ~fb : (fb | 0x80000000u);
                        unsigned long long key =
                            ((unsigned long long)fb << 32) | (unsigned)(0x7FFFFFFFu - jb);
                        if(key > best) best = key;
                    }
                }
            }
            if(is4) sm.u.fc.wb[w*8 + bmap] = best;
            __syncthreads();
            if(tid < BB){
                unsigned long long bb = 0ull;
#pragma unroll
                for(int ww=0; ww<NW; ww++){
                    unsigned long long k = sm.u.fc.wb[ww*8 + tid];
                    if(k > bb) bb = k;
                }
                atomicMax(&g_am[tid], bb);
            }
            // coalesced logit writeback
            for(int b=0;b<BB;b++){
                float* op = out + ((size_t)b*STEPS + t)*VV + base;
                for(int rr=tid; rr<nrows; rr+=NT) op[rr] = sm.u.fc.logit[b][rr];
            }
        }
        gbar();
    } // steps
}

// ---------------- launch ----------------
extern "C" void kernel_launch(void* const* d_in, const int* in_sizes, int n_in,
                              void* d_out, int out_size){
    const float* embedding = (const float*)d_in[0];
    const float* w_proj    = (const float*)d_in[1];
    const float* b_proj    = (const float*)d_in[2];
    const float* tok_emb   = (const float*)d_in[3];
    const float* pos_enc   = (const float*)d_in[4];
    const float* sa_in_w   = (const float*)d_in[5];
    const float* sa_in_b   = (const float*)d_in[6];
    const float* sa_out_w  = (const float*)d_in[7];
    const float* sa_out_b  = (const float*)d_in[8];
    const float* ca_in_w   = (const float*)d_in[9];
    const float* ca_in_b   = (const float*)d_in[10];
    const float* ca_out_w  = (const float*)d_in[11];
    const float* ca_out_b  = (const float*)d_in[12];
    const float* ff1_w     = (const float*)d_in[13];
    const float* ff1_b     = (const float*)d_in[14];
    const float* ff2_w     = (const float*)d_in[15];
    const float* ff2_b     = (const float*)d_in[16];
    const float* ln_g      = (const float*)d_in[17];
    const float* ln_b      = (const float*)d_in[18];
    const float* fc_w      = (const float*)d_in[19];
    const float* fc_b      = (const float*)d_in[20];
    float* out = (float*)d_out;

    mega<<<NB, NT>>>(embedding, w_proj, b_proj, tok_emb, pos_enc,
                     sa_in_w, sa_in_b, sa_out_w, sa_out_b,
                     ca_in_w, ca_in_b, ca_out_w, ca_out_b,
                     ff1_w, ff1_b, ff2_w, ff2_b, ln_g, ln_b,
                     fc_w, fc_b, out);
}

// round 6
// speedup vs baseline: 1.6378x; 1.1781x over previous
#include <cuda_runtime.h>
#include <cstdint>
#include <cstddef>

// Problem constants
#define BB   8
#define HH   256
#define NHH  8
#define HDD  32
#define LL   50
#define VV   50257
#define NLL  4
#define FFF  2048
#define EE   1536
#define BOSTOK 50256
#define STEPS 49
#define EPSLN 1e-5f

// Persistent-kernel config
#define NB   128     // blocks (co-resident)
#define NT   512     // threads per block (16 warps)
#define NW   16      // warps per block
#define GPB  16      // blocks per batch group
#define RPB  393     // FC rows per block: 128*393 = 50304 >= VV

// ---------------- device scratch ----------------
__device__ float g_mem_[BB*HH];
__device__ float g_tmpv[NLL*BB*HH];
__device__ float g_ca  [NLL*BB*HH];             // cross-attn constant per layer
__device__ float g_q   [BB*HH];
__device__ float g_Kc  [NLL*BB*LL*HH];          // K cache
__device__ float g_Vc  [NLL*BB*LL*HH];          // V cache
__device__ float g_pr  [BB*HH];                 // attn out-proj output
__device__ float g_x2  [NLL*BB*HH];             // x2 per layer (for FC)
__device__ float g_yb  [NLL*BB*HH];             // FFN output per layer
__device__ float g_hbuf[BB*FFF];                // FFN hidden
__device__ unsigned long long g_am[BB];         // packed argmax
// grid barrier (two-level, groups of 8)
__device__ unsigned g_cntg[16*32];
__device__ unsigned g_cnt0;
__device__ unsigned g_gen;
// per-batch group barriers (own cache line each)
__device__ unsigned g_bcnt[BB*32];
__device__ unsigned g_bgen[BB*32];

// ---------------- helpers ----------------
__device__ __forceinline__ float wred(float v){
#pragma unroll
    for(int o=16;o;o>>=1) v += __shfl_xor_sync(0xffffffffu, v, o);
    return v;
}
__device__ __forceinline__ float wredmax(float v){
#pragma unroll
    for(int o=16;o;o>>=1) v = fmaxf(v, __shfl_xor_sync(0xffffffffu, v, o));
    return v;
}

// Reduce 8 per-lane partials across warp; lane-group g gets batch
// bmap = 4*bit4 + 2*bit3 + bit2. (used in setup + FC)
__device__ __forceinline__ float red8(float a[8], int lane){
#pragma unroll
    for(int b=0;b<4;b++){
        float send = (lane&16)? a[b] : a[b+4];
        float got  = __shfl_xor_sync(0xffffffffu, send, 16);
        a[b] = ((lane&16)? a[b+4] : a[b]) + got;
    }
#pragma unroll
    for(int b=0;b<2;b++){
        float send = (lane&8)? a[b] : a[b+2];
        float got  = __shfl_xor_sync(0xffffffffu, send, 8);
        a[b] = ((lane&8)? a[b+2] : a[b]) + got;
    }
    {
        float send = (lane&4)? a[0] : a[1];
        float got  = __shfl_xor_sync(0xffffffffu, send, 4);
        a[0] = ((lane&4)? a[1] : a[0]) + got;
    }
    a[0] += __shfl_xor_sync(0xffffffffu, a[0], 2);
    a[0] += __shfl_xor_sync(0xffffffffu, a[0], 1);
    return a[0];
}

// Grid-wide tree barrier (all 128 blocks).
__device__ __forceinline__ void gbar(){
    __syncthreads();
    if(threadIdx.x==0){
        volatile unsigned* vg = (volatile unsigned*)&g_gen;
        unsigned gen = *vg;
        __threadfence();
        int grp = blockIdx.x >> 3;
        unsigned a = atomicAdd(&g_cntg[grp*32], 1u);
        bool released = false;
        if(a == 7u){
            *(volatile unsigned*)&g_cntg[grp*32] = 0u;
            unsigned r = atomicAdd(&g_cnt0, 1u);
            if(r == 15u){
                *(volatile unsigned*)&g_cnt0 = 0u;
                __threadfence();
                atomicAdd(&g_gen, 1u);
                released = true;
            }
        }
        if(!released){
            while(*vg == gen){ __nanosleep(32); }
        }
        __threadfence();
    }
    __syncthreads();
}

// Group barrier: the 16 blocks of batch b.
__device__ __forceinline__ void gbarb(int b){
    __syncthreads();
    if(threadIdx.x==0){
        volatile unsigned* vg = (volatile unsigned*)&g_bgen[b*32];
        unsigned gen = *vg;
        __threadfence();
        unsigned a = atomicAdd(&g_bcnt[b*32], 1u);
        if(a == GPB-1u){
            *(volatile unsigned*)&g_bcnt[b*32] = 0u;
            __threadfence();
            atomicAdd(&g_bgen[b*32], 1u);
        }else{
            while(*vg == gen){ __nanosleep(32); }
        }
        __threadfence();
    }
    __syncthreads();
}

// In-place warp LayerNorm of a 256-wide row held as 8 per-lane values.
__device__ __forceinline__ void ln_reg(float v[8], const float* __restrict__ g,
                                       const float* __restrict__ b, int lane){
    float s=0.f, ss=0.f;
#pragma unroll
    for(int i=0;i<8;i++){ s += v[i]; ss += v[i]*v[i]; }
    s  = wred(s);
    ss = wred(ss);
    float m   = s * (1.f/HH);
    float var = ss * (1.f/HH) - m*m;
    float r   = rsqrtf(var + EPSLN);
#pragma unroll
    for(int i=0;i<8;i++){
        int c = lane + 32*i;
        v[i] = (v[i]-m)*r*g[c] + b[c];
    }
}

struct __align__(16) SMem {
    float xs0[HH];                               // this group's x2 of prev layer
    union {
        struct { float qs[HH]; float ps[NHH][64]; float ao[HH]; } at;
        float h2[FFF];                           // ff2 staging (8KB)
        struct { float xs[BB][HH]; float logit[BB][400];
                 unsigned long long wb[NW*8]; } fc;
    } u;
};

__global__ void __launch_bounds__(NT, 1)
mega(const float* __restrict__ embedding, const float* __restrict__ w_proj,
     const float* __restrict__ b_proj,    const float* __restrict__ tok_emb,
     const float* __restrict__ pos_enc,   const float* __restrict__ sa_in_w,
     const float* __restrict__ sa_in_b,   const float* __restrict__ sa_out_w,
     const float* __restrict__ sa_out_b,  const float* __restrict__ ca_in_w,
     const float* __restrict__ ca_in_b,   const float* __restrict__ ca_out_w,
     const float* __restrict__ ca_out_b,  const float* __restrict__ ff1_w,
     const float* __restrict__ ff1_b,     const float* __restrict__ ff2_w,
     const float* __restrict__ ff2_b,     const float* __restrict__ ln_g,
     const float* __restrict__ ln_b,      const float* __restrict__ fc_w,
     const float* __restrict__ fc_b,      float* __restrict__ out)
{
    __shared__ SMem sm;
    const int tid  = threadIdx.x;
    const int w    = tid >> 5;
    const int lane = tid & 31;
    const int bl   = blockIdx.x;
    const int gw   = bl*NW + w;                 // global warp id 0..2047
    const int bt   = bl >> 4;                   // batch owned by this group
    const int lb   = bl & 15;                   // local block in group
    const int gw2  = lb*NW + w;                 // warp id within group 0..255
    const int bmap = ((lane>>4)&1)*4 + ((lane>>3)&1)*2 + ((lane>>2)&1);
    const bool is4 = (lane&3)==0;

    // ================= setup =================
    if(gw < HH){
        int j = gw;
        const float* wr = w_proj + (size_t)j*EE;
        float acc[8];
#pragma unroll
        for(int b=0;b<BB;b++) acc[b]=0.f;
        for(int i=lane;i<EE;i+=32){
            float wv = wr[i];
#pragma unroll
            for(int b=0;b<BB;b++) acc[b] += wv*embedding[b*EE+i];
        }
        float tot = red8(acc, lane);
        if(is4) g_mem_[bmap*HH + j] = tot + b_proj[j];
    }
    gbar();
    if(gw < NLL*HH){
        int l = gw>>8, j = gw&255;
        const float* wr = ca_in_w + ((size_t)l*3*HH + 2*HH + j)*HH;
        float acc[8];
#pragma unroll
        for(int b=0;b<BB;b++) acc[b]=0.f;
#pragma unroll
        for(int k=0;k<8;k++){
            int i = lane + 32*k;
            float wv = wr[i];
#pragma unroll
            for(int b=0;b<BB;b++) acc[b] += wv*g_mem_[b*HH+i];
        }
        float tot = red8(acc, lane);
        if(is4) g_tmpv[(l*BB+bmap)*HH + j] = tot + ca_in_b[l*3*HH + 2*HH + j];
    }
    gbar();
    if(gw < NLL*HH){
        int l = gw>>8, j = gw&255;
        const float* wr = ca_out_w + ((size_t)l*HH + j)*HH;
        float acc[8];
#pragma unroll
        for(int b=0;b<BB;b++) acc[b]=0.f;
#pragma unroll
        for(int k=0;k<8;k++){
            int i = lane + 32*k;
            float wv = wr[i];
#pragma unroll
            for(int b=0;b<BB;b++) acc[b] += wv*g_tmpv[(l*BB+b)*HH+i];
        }
        float tot = red8(acc, lane);
        if(is4) g_ca[(l*BB+bmap)*HH + j] = tot + ca_out_b[l*HH + j];
    }
    gbar();

    // ================= decode steps =================
    for(int t=0; t<STEPS; t++){
        for(int l=0; l<NLL; l++){
            // ---- phase A: x_in (redundant per warp) + QKV rows (3/warp) ----
            float xin[8];
            {
                if(l==0){
                    if(lb==0 && tid==0 && t==0) ; // no-op
                    int tok = (t==0) ? BOSTOK
                        : (int)(0x7FFFFFFFu - (unsigned)(g_am[bt] & 0xFFFFFFFFull));
                    const float* te = tok_emb + (size_t)tok*HH;
                    const float* pe = pos_enc + (size_t)t*HH;
#pragma unroll
                    for(int i=0;i<8;i++){ int c=lane+32*i; xin[i] = te[c]+pe[c]; }
                }else{
#pragma unroll
                    for(int i=0;i<8;i++){
                        int c=lane+32*i;
                        xin[i] = sm.xs0[c] + g_yb[((l-1)*BB+bt)*HH+c];
                    }
                    ln_reg(xin, ln_g+((l-1)*3+2)*HH, ln_b+((l-1)*3+2)*HH, lane);
                }
                if(l==1 && lb==0 && tid==0) g_am[bt] = 0ull;  // reset for FC
                // 3 rows per warp: q row, K row, V row
                float wreg[3][8];
#pragma unroll
                for(int rr=0;rr<3;rr++){
                    const float* wr = sa_in_w + ((size_t)l*3*HH + gw2 + rr*HH)*HH;
#pragma unroll
                    for(int i=0;i<8;i++) wreg[rr][i] = wr[lane+32*i];
                }
#pragma unroll
                for(int rr=0;rr<3;rr++){
                    int j = gw2 + rr*HH;
                    float s=0.f;
#pragma unroll
                    for(int i=0;i<8;i++) s += wreg[rr][i]*xin[i];
                    s = wred(s);
                    if(lane==0){
                        s += sa_in_b[l*3*HH + j];
                        if(rr==0)      g_q [bt*HH + gw2] = s;
                        else if(rr==1) g_Kc[((size_t)(l*BB+bt)*LL + t)*HH + gw2] = s;
                        else           g_Vc[((size_t)(l*BB+bt)*LL + t)*HH + gw2] = s;
                    }
                }
            }
            gbarb(bt);
            // ---- phase B: attention + out-projection (block lb==0 only) ----
            if(lb == 0){
                int n = t+1;
                if(w < NHH){
                    int h = w;
                    sm.u.at.qs[h*32+lane] = g_q[bt*HH + h*32 + lane];
                    __syncwarp();
                    const float* Kb = g_Kc + ((size_t)(l*BB+bt)*LL)*HH + h*HDD;
                    float sc0=-1e30f, sc1=-1e30f;
                    int i0=lane, i1=lane+32;
                    if(i0<n){
                        const float4* kr = (const float4*)(Kb + (size_t)i0*HH);
                        float s=0.f;
#pragma unroll
                        for(int r=0;r<8;r++){
                            float4 kv = kr[r];
                            s += kv.x*sm.u.at.qs[h*32+4*r+0] + kv.y*sm.u.at.qs[h*32+4*r+1]
                               + kv.z*sm.u.at.qs[h*32+4*r+2] + kv.w*sm.u.at.qs[h*32+4*r+3];
                        }
                        sc0 = s * 0.17677669529663688f;
                    }
                    if(i1<n){
                        const float4* kr = (const float4*)(Kb + (size_t)i1*HH);
                        float s=0.f;
#pragma unroll
                        for(int r=0;r<8;r++){
                            float4 kv = kr[r];
                            s += kv.x*sm.u.at.qs[h*32+4*r+0] + kv.y*sm.u.at.qs[h*32+4*r+1]
                               + kv.z*sm.u.at.qs[h*32+4*r+2] + kv.w*sm.u.at.qs[h*32+4*r+3];
                        }
                        sc1 = s * 0.17677669529663688f;
                    }
                    float mx = wredmax(fmaxf(sc0, sc1));
                    float p0 = (i0<n)? expf(sc0-mx) : 0.f;
                    float p1 = (i1<n)? expf(sc1-mx) : 0.f;
                    float sum = wred(p0+p1);
                    sm.u.at.ps[h][lane]    = p0;
                    sm.u.at.ps[h][lane+32] = p1;
                    __syncwarp();
                    const float* Vb = g_Vc + ((size_t)(l*BB+bt)*LL)*HH + h*HDD + lane;
                    float o0=0.f,o1=0.f,o2=0.f,o3=0.f;
                    int i=0;
                    for(; i+4<=n; i+=4){
                        o0 += sm.u.at.ps[h][i+0] * Vb[(size_t)(i+0)*HH];
                        o1 += sm.u.at.ps[h][i+1] * Vb[(size_t)(i+1)*HH];
                        o2 += sm.u.at.ps[h][i+2] * Vb[(size_t)(i+2)*HH];
                        o3 += sm.u.at.ps[h][i+3] * Vb[(size_t)(i+3)*HH];
                    }
                    for(; i<n; i++) o0 += sm.u.at.ps[h][i] * Vb[(size_t)i*HH];
                    sm.u.at.ao[h*HDD + lane] = ((o0+o1)+(o2+o3)) / sum;
                }
                __syncthreads();
                // out-projection over 16 warps
                for(int j=w; j<HH; j+=NW){
                    const float* wr = sa_out_w + ((size_t)l*HH + j)*HH;
                    float s=0.f;
#pragma unroll
                    for(int i=0;i<8;i++) s += wr[lane+32*i]*sm.u.at.ao[lane+32*i];
                    s = wred(s);
                    if(lane==0) g_pr[bt*HH + j] = s + sa_out_b[l*HH + j];
                }
            }
            gbarb(bt);
            // ---- phase D: LN chain (redundant per warp) -> x2, FF1 8 rows/warp ----
            {
                float v[8];
#pragma unroll
                for(int i=0;i<8;i++) v[i] = xin[i] + g_pr[bt*HH + lane+32*i];
                ln_reg(v, ln_g+(l*3+0)*HH, ln_b+(l*3+0)*HH, lane);
#pragma unroll
                for(int i=0;i<8;i++) v[i] += g_ca[(l*BB+bt)*HH + lane+32*i];
                ln_reg(v, ln_g+(l*3+1)*HH, ln_b+(l*3+1)*HH, lane);
                if(w==0){
#pragma unroll
                    for(int i=0;i<8;i++) sm.xs0[lane+32*i] = v[i];   // x2 for next layer
                    if(lb==0){
#pragma unroll
                        for(int i=0;i<8;i++) g_x2[(l*BB+bt)*HH + lane+32*i] = v[i];
                    }
                }
                // FF1: rows gw2 + rr*256, rr<8, batched by 2
#pragma unroll
                for(int rr=0; rr<8; rr+=2){
                    int j0 = gw2 + rr*HH, j1 = j0 + HH;
                    const float* w0 = ff1_w + ((size_t)l*FFF + j0)*HH;
                    const float* w1 = ff1_w + ((size_t)l*FFF + j1)*HH;
                    float wa[8], wb2[8];
#pragma unroll
                    for(int i=0;i<8;i++){ wa[i]=w0[lane+32*i]; wb2[i]=w1[lane+32*i]; }
                    float a0=0.f, a1=0.f;
#pragma unroll
                    for(int i=0;i<8;i++){ a0 += wa[i]*v[i]; a1 += wb2[i]*v[i]; }
                    a0 = wred(a0);
                    a1 = wred(a1);
                    if(lane==0){
                        g_hbuf[bt*FFF + j0] = fmaxf(a0 + ff1_b[l*FFF + j0], 0.f);
                        g_hbuf[bt*FFF + j1] = fmaxf(a1 + ff1_b[l*FFF + j1], 0.f);
                    }
                }
            }
            gbarb(bt);
            // ---- phase E: FF2, 1 row/warp over 2048 (smem-staged hidden) ----
            {
                {
                    float4* dst = (float4*)sm.u.h2;
                    const float4* src = (const float4*)(g_hbuf + bt*FFF);
                    dst[tid] = src[tid];           // 512 float4 = 2048 floats
                }
                __syncthreads();
                int j = gw2;
                const float4* wr4 = (const float4*)(ff2_w + ((size_t)l*HH + j)*FFF);
                const float4* h4  = (const float4*)sm.u.h2;
                float a0=0.f, a1=0.f;
#pragma unroll
                for(int i=0;i<16;i+=2){
                    float4 wv0 = wr4[lane+32*i],     hv0 = h4[lane+32*i];
                    float4 wv1 = wr4[lane+32*(i+1)], hv1 = h4[lane+32*(i+1)];
                    a0 += wv0.x*hv0.x + wv0.y*hv0.y + wv0.z*hv0.z + wv0.w*hv0.w;
                    a1 += wv1.x*hv1.x + wv1.y*hv1.y + wv1.z*hv1.z + wv1.w*hv1.w;
                }
                float s = wred(a0+a1);
                if(lane==0) g_yb[(l*BB+bt)*HH + j] = s + ff2_b[l*HH + j];
            }
            gbarb(bt);
        } // layers

        gbar();
        // ---- phase FC: logits + argmax (all blocks, all batches) ----
        {
            if(w < BB){
                float v[8];
#pragma unroll
                for(int i=0;i<8;i++){
                    int c=lane+32*i;
                    v[i] = g_x2[(3*BB+w)*HH+c] + g_yb[(3*BB+w)*HH+c];
                }
                ln_reg(v, ln_g+(3*3+2)*HH, ln_b+(3*3+2)*HH, lane);
#pragma unroll
                for(int i=0;i<8;i++) sm.u.fc.xs[w][lane+32*i] = v[i];
            }
            __syncthreads();

            float4 xr[BB][2];
#pragma unroll
            for(int b=0;b<BB;b++){
                const float4* xp = (const float4*)sm.u.fc.xs[b];
                xr[b][0] = xp[lane];
                xr[b][1] = xp[lane+32];
            }
            int base  = bl*RPB;
            int nrows = VV - base; if(nrows > RPB) nrows = RPB;
            unsigned long long best = 0ull;
            for(int r=w; r<RPB; r+=2*NW){
                int ja = base + r;
                int rb = r + NW;
                int jb = base + rb;
                bool va = (ja < VV), vb = (rb < RPB) && (jb < VV);
                float4 wa0, wa1, wb0, wb1;
                if(va){
                    const float4* wr4 = (const float4*)(fc_w + (size_t)ja*HH);
                    wa0 = wr4[lane]; wa1 = wr4[lane+32];
                }
                if(vb){
                    const float4* wr4 = (const float4*)(fc_w + (size_t)jb*HH);
                    wb0 = wr4[lane]; wb1 = wr4[lane+32];
                }
                if(va){
                    float acc[8];
#pragma unroll
                    for(int b=0;b<BB;b++){
                        float4 x0 = xr[b][0], x1 = xr[b][1];
                        acc[b] = wa0.x*x0.x + wa0.y*x0.y + wa0.z*x0.z + wa0.w*x0.w
                               + wa1.x*x1.x + wa1.y*x1.y + wa1.z*x1.z + wa1.w*x1.w;
                    }
                    float tot = red8(acc, lane);
                    if(is4){
                        float s = tot + fc_b[ja];
                        sm.u.fc.logit[bmap][r] = s;
                        unsigned fb = __float_as_uint(s);
                        fb = (fb & 0x80000000u) ? ~fb : (fb | 0x80000000u);
                        unsigned long long key =
                            ((unsigned long long)fb << 32) | (unsigned)(0x7FFFFFFFu - ja);
                        if(key > best) best = key;
                    }
                }
                if(vb){
                    float acc[8];
#pragma unroll
                    for(int b=0;b<BB;b++){
                        float4 x0 = xr[b][0], x1 = xr[b][1];
                        acc[b] = wb0.x*x0.x + wb0.y*x0.y + wb0.z*x0.z + wb0.w*x0.w
                               + wb1.x*x1.x + wb1.y*x1.y + wb1.z*x1.z + wb1.w*x1.w;
                    }
                    float tot = red8(acc, lane);
                    if(is4){
                        float s = tot + fc_b[jb];
                        sm.u.fc.logit[bmap][rb] = s;
                        unsigned fb = __float_as_uint(s);
                        fb = (fb & 0x80000000u) ? ~fb : (fb | 0x80000000u);
                        unsigned long long key =
                            ((unsigned long long)fb << 32) | (unsigned)(0x7FFFFFFFu - jb);
                        if(key > best) best = key;
                    }
                }
            }
            if(is4) sm.u.fc.wb[w*8 + bmap] = best;
            __syncthreads();
            if(tid < BB){
                unsigned long long bb = 0ull;
#pragma unroll
                for(int ww=0; ww<NW; ww++){
                    unsigned long long k = sm.u.fc.wb[ww*8 + tid];
                    if(k > bb) bb = k;
                }
                atomicMax(&g_am[tid], bb);
            }
            for(int b=0;b<BB;b++){
                float* op = out + ((size_t)b*STEPS + t)*VV + base;
                for(int rr=tid; rr<nrows; rr+=NT) op[rr] = sm.u.fc.logit[b][rr];
            }
        }
        gbar();
    } // steps
}

// ---------------- launch ----------------
extern "C" void kernel_launch(void* const* d_in, const int* in_sizes, int n_in,
                              void* d_out, int out_size){
    const float* embedding = (const float*)d_in[0];
    const float* w_proj    = (const float*)d_in[1];
    const float* b_proj    = (const float*)d_in[2];
    const float* tok_emb   = (const float*)d_in[3];
    const float* pos_enc   = (const float*)d_in[4];
    const float* sa_in_w   = (const float*)d_in[5];
    const float* sa_in_b   = (const float*)d_in[6];
    const float* sa_out_w  = (const float*)d_in[7];
    const float* sa_out_b  = (const float*)d_in[8];
    const float* ca_in_w   = (const float*)d_in[9];
    const float* ca_in_b   = (const float*)d_in[10];
    const float* ca_out_w  = (const float*)d_in[11];
    const float* ca_out_b  = (const float*)d_in[12];
    const float* ff1_w     = (const float*)d_in[13];
    const float* ff1_b     = (const float*)d_in[14];
    const float* ff2_w     = (const float*)d_in[15];
    const float* ff2_b     = (const float*)d_in[16];
    const float* ln_g      = (const float*)d_in[17];
    const float* ln_b      = (const float*)d_in[18];
    const float* fc_w      = (const float*)d_in[19];
    const float* fc_b      = (const float*)d_in[20];
    float* out = (float*)d_out;

    mega<<<NB, NT>>>(embedding, w_proj, b_proj, tok_emb, pos_enc,
                     sa_in_w, sa_in_b, sa_out_w, sa_out_b,
                     ca_in_w, ca_in_b, ca_out_w, ca_out_b,
                     ff1_w, ff1_b, ff2_w, ff2_b, ln_g, ln_b,
                     fc_w, fc_b, out);
}